// round 2
// baseline (speedup 1.0000x reference)
#include <cuda_runtime.h>
#include <math.h>

#define CC 64
#define HH 64
#define WWD 64
#define NN 4096
#define BB 4
#define NELEM (BB*CC*NN)

// ---------------- scratch (static device memory; no allocs allowed) ----------
// layout (floats): raw(1M) x1(1M) theta_t(1M) phi(1M) g_t(1M) y(1M) z(1M) wt(36864) scale(64) shift(64)
__device__ float g_buf[8u * 1024u * 1024u];

static const size_t OFF_RAW = 0;
static const size_t OFF_X1  = 1u << 20;
static const size_t OFF_TH  = 2u << 20;
static const size_t OFF_PHI = 3u << 20;
static const size_t OFF_G   = 4u << 20;
static const size_t OFF_Y   = 5u << 20;
static const size_t OFF_Z   = 6u << 20;
static const size_t OFF_WT  = 7u << 20;
static const size_t OFF_SC  = OFF_WT + 40960;
static const size_t OFF_SH  = OFF_SC + 64;

// ---------------- weight transpose: w[oc][ic][k] -> wt[(ic*9+k)*64 + oc] -----
__global__ void wtrans_kernel(const float* __restrict__ w, float* __restrict__ wt) {
    int i = blockIdx.x * 256 + threadIdx.x;          // 36864 total
    if (i >= CC * CC * 9) return;
    int oc  = i / (CC * 9);
    int rem = i - oc * (CC * 9);                     // ic*9 + k
    wt[rem * CC + oc] = w[i];
}

// ---------------- 3x3 conv, pad=1 ------------------------------------------
// grid (W/16, H/8, B), 256 threads.
// thread: pixel-col px (0..15), 4 rows starting at py, 8 output channels oc0..oc0+7
__global__ void __launch_bounds__(256) conv3x3_kernel(
    const float* __restrict__ in, const float* __restrict__ wt,
    const float* __restrict__ bias, float* __restrict__ out, int transpose_out)
{
    __shared__ __align__(16) float in_s[8][10][18];   // [ic][row][col]
    __shared__ __align__(16) float w_s[8 * 9 * 64];   // [(ic*9+k)*64 + oc]

    int b   = blockIdx.z;
    int ty0 = blockIdx.y * 8;
    int tx0 = blockIdx.x * 16;
    int tid = threadIdx.x;
    int pt  = tid & 31;
    int px  = pt & 15;
    int py  = (pt >> 4) * 4;
    int oc0 = (tid >> 5) * 8;

    float acc[4][8];
#pragma unroll
    for (int i = 0; i < 4; i++)
#pragma unroll
        for (int j = 0; j < 8; j++) acc[i][j] = 0.f;

    for (int ic0 = 0; ic0 < CC; ic0 += 8) {
        // load input chunk with zero padding
        for (int i = tid; i < 8 * 10 * 18; i += 256) {
            int ic  = i / 180;
            int rem = i - ic * 180;
            int r   = rem / 18;
            int c   = rem - r * 18;
            int gy  = ty0 + r - 1;
            int gx  = tx0 + c - 1;
            float v = 0.f;
            if (gy >= 0 && gy < HH && gx >= 0 && gx < WWD)
                v = in[((size_t)(b * CC + ic0 + ic) * HH + gy) * WWD + gx];
            in_s[ic][r][c] = v;
        }
        // load weight chunk (contiguous)
        for (int i = tid; i < 8 * 9 * 64; i += 256)
            w_s[i] = wt[ic0 * 9 * 64 + i];
        __syncthreads();

#pragma unroll 2
        for (int ic = 0; ic < 8; ic++) {
#pragma unroll
            for (int ky = 0; ky < 3; ky++) {
#pragma unroll
                for (int kx = 0; kx < 3; kx++) {
                    const float* wb = &w_s[(ic * 9 + ky * 3 + kx) * 64 + oc0];
                    float4 wa = *(const float4*)wb;
                    float4 wc = *(const float4*)(wb + 4);
#pragma unroll
                    for (int i = 0; i < 4; i++) {
                        float v = in_s[ic][py + i + ky][px + kx];
                        acc[i][0] = fmaf(v, wa.x, acc[i][0]);
                        acc[i][1] = fmaf(v, wa.y, acc[i][1]);
                        acc[i][2] = fmaf(v, wa.z, acc[i][2]);
                        acc[i][3] = fmaf(v, wa.w, acc[i][3]);
                        acc[i][4] = fmaf(v, wc.x, acc[i][4]);
                        acc[i][5] = fmaf(v, wc.y, acc[i][5]);
                        acc[i][6] = fmaf(v, wc.z, acc[i][6]);
                        acc[i][7] = fmaf(v, wc.w, acc[i][7]);
                    }
                }
            }
        }
        __syncthreads();
    }

    float bv[8];
#pragma unroll
    for (int j = 0; j < 8; j++) bv[j] = bias ? bias[oc0 + j] : 0.f;

#pragma unroll
    for (int i = 0; i < 4; i++) {
        int gy = ty0 + py + i;
        int gx = tx0 + px;
        int n  = gy * WWD + gx;
#pragma unroll
        for (int j = 0; j < 8; j++) {
            float v = acc[i][j] + bv[j];
            if (transpose_out)
                out[((size_t)b * NN + n) * CC + oc0 + j] = v;          // [B,N,C]
            else
                out[((size_t)(b * CC + oc0 + j) << 12) + n] = v;       // [B,C,N]
        }
    }
}

// ---------------- BN stats: per-channel scale/shift (training-mode, biased) --
__global__ void bn_stats_kernel(const float* __restrict__ in,
                                const float* __restrict__ gamma,
                                const float* __restrict__ beta,
                                float* __restrict__ scale, float* __restrict__ shift)
{
    int c = blockIdx.x;
    int tid = threadIdx.x;
    float s = 0.f, s2 = 0.f;
    for (int b = 0; b < BB; b++) {
        const float* p = in + (((size_t)(b * CC + c)) << 12);
        for (int i = tid; i < NN; i += 256) {
            float v = p[i];
            s += v; s2 += v * v;
        }
    }
    __shared__ float sh[256], sh2[256];
    sh[tid] = s; sh2[tid] = s2;
    __syncthreads();
    for (int o = 128; o > 0; o >>= 1) {
        if (tid < o) { sh[tid] += sh[tid + o]; sh2[tid] += sh2[tid + o]; }
        __syncthreads();
    }
    if (tid == 0) {
        const float inv = 1.f / (float)(BB * NN);
        float mean = sh[0] * inv;
        float var  = sh2[0] * inv - mean * mean;
        float r    = rsqrtf(var + 1e-5f);
        float sc   = gamma[c] * r;
        scale[c] = sc;
        shift[c] = beta[c] - mean * sc;
    }
}

__global__ void bn_apply_relu_kernel(const float* __restrict__ in,
                                     const float* __restrict__ scale,
                                     const float* __restrict__ shift,
                                     float* __restrict__ out)
{
    int i = blockIdx.x * 256 + threadIdx.x;
    int c = (i >> 12) & 63;
    float v = fmaf(in[i], scale[c], shift[c]);
    out[i] = fmaxf(v, 0.f);
}

// ---------------- flash attention: y = softmax(Q K) G ------------------------
// Qt: [B,N,C], K(phi): [B,C,N], Gt: [B,N,C] -> Y: [B,C,N]
// block: 128 threads, 64 query rows. tx = tid&7 (8 m/c cols), ty = tid>>3 (4 q rows)
#define FP 68  // smem pitch
__global__ void __launch_bounds__(128) flash_kernel(
    const float* __restrict__ Qt, const float* __restrict__ K,
    const float* __restrict__ Gt, float* __restrict__ Y)
{
    extern __shared__ __align__(16) float sm[];
    float* Qs = sm;                 // [c][q]
    float* Ks = sm + 64 * FP;       // [c][m]
    float* Ps = sm + 2 * 64 * FP;   // [m][q]  (also reused as [q][c] out-stage)
    float* Gs = sm + 3 * 64 * FP;   // [m][c]
    float* row_m = sm + 4 * 64 * FP;
    float* row_l = row_m + 64;

    int b  = blockIdx.y;
    int n0 = blockIdx.x * 64;
    int tid = threadIdx.x;
    int tx = tid & 7;
    int ty = tid >> 3;

    // load Q transposed into [c][q]
    for (int i = tid; i < 4096; i += 128) {
        int q = i >> 6, c = i & 63;
        Qs[c * FP + q] = Qt[((size_t)b * NN + n0 + q) * CC + c];
    }
    if (tid < 64) { row_m[tid] = -1e30f; row_l[tid] = 0.f; }

    float O[4][8];
#pragma unroll
    for (int i = 0; i < 4; i++)
#pragma unroll
        for (int j = 0; j < 8; j++) O[i][j] = 0.f;

    for (int j0 = 0; j0 < NN; j0 += 64) {
        __syncthreads();  // protect Ks/Gs/Ps reuse; covers Q/row init on iter 0
        for (int i = tid; i < 4096; i += 128) {
            int r = i >> 6, c = i & 63;
            Ks[r * FP + c] = K[(((size_t)(b * CC + r)) << 12) + j0 + c];
            Gs[r * FP + c] = Gt[((size_t)b * NN + j0 + r) * CC + c];
        }
        __syncthreads();

        // S = Q K  (4q x 8m per thread)
        float s[4][8];
#pragma unroll
        for (int i = 0; i < 4; i++)
#pragma unroll
            for (int j = 0; j < 8; j++) s[i][j] = 0.f;

        for (int c = 0; c < 64; c++) {
            float4 qv = *(const float4*)&Qs[c * FP + ty * 4];
            float4 ka = *(const float4*)&Ks[c * FP + tx * 8];
            float4 kb = *(const float4*)&Ks[c * FP + tx * 8 + 4];
            float q[4] = {qv.x, qv.y, qv.z, qv.w};
            float k[8] = {ka.x, ka.y, ka.z, ka.w, kb.x, kb.y, kb.z, kb.w};
#pragma unroll
            for (int i = 0; i < 4; i++)
#pragma unroll
                for (int j = 0; j < 8; j++) s[i][j] = fmaf(q[i], k[j], s[i][j]);
        }

        // online softmax per q-row
        float mnew[4], alpha[4], rsum[4];
#pragma unroll
        for (int i = 0; i < 4; i++) {
            float mx = s[i][0];
#pragma unroll
            for (int j = 1; j < 8; j++) mx = fmaxf(mx, s[i][j]);
            for (int o = 4; o > 0; o >>= 1)
                mx = fmaxf(mx, __shfl_xor_sync(0xffffffffu, mx, o));
            float mo = row_m[ty * 4 + i];
            float mn = fmaxf(mo, mx);
            mnew[i]  = mn;
            alpha[i] = __expf(mo - mn);
        }
#pragma unroll
        for (int i = 0; i < 4; i++) {
            float rs = 0.f;
#pragma unroll
            for (int j = 0; j < 8; j++) {
                float p = __expf(s[i][j] - mnew[i]);
                Ps[(tx * 8 + j) * FP + ty * 4 + i] = p;   // P transposed [m][q]
                rs += p;
            }
            for (int o = 4; o > 0; o >>= 1)
                rs += __shfl_xor_sync(0xffffffffu, rs, o);
            rsum[i] = rs;
        }
        __syncwarp();
        if (tx == 0) {
#pragma unroll
            for (int i = 0; i < 4; i++) {
                int q = ty * 4 + i;
                row_m[q] = mnew[i];
                row_l[q] = row_l[q] * alpha[i] + rsum[i];
            }
        }
#pragma unroll
        for (int i = 0; i < 4; i++)
#pragma unroll
            for (int j = 0; j < 8; j++) O[i][j] *= alpha[i];
        __syncthreads();

        // O += P G
        for (int m = 0; m < 64; m++) {
            float4 pv = *(const float4*)&Ps[m * FP + ty * 4];
            float4 ga = *(const float4*)&Gs[m * FP + tx * 8];
            float4 gb = *(const float4*)&Gs[m * FP + tx * 8 + 4];
            float p[4] = {pv.x, pv.y, pv.z, pv.w};
            float g[8] = {ga.x, ga.y, ga.z, ga.w, gb.x, gb.y, gb.z, gb.w};
#pragma unroll
            for (int i = 0; i < 4; i++)
#pragma unroll
                for (int j = 0; j < 8; j++) O[i][j] = fmaf(p[i], g[j], O[i][j]);
        }
    }
    __syncthreads();

    float linv[4];
#pragma unroll
    for (int i = 0; i < 4; i++) linv[i] = 1.f / row_l[ty * 4 + i];

    // stage O as [q][c] then write Y[B,C,N] coalesced
#pragma unroll
    for (int i = 0; i < 4; i++)
#pragma unroll
        for (int j = 0; j < 8; j++)
            Ps[(ty * 4 + i) * FP + tx * 8 + j] = O[i][j] * linv[i];
    __syncthreads();
    for (int i = tid; i < 4096; i += 128) {
        int c = i >> 6, q = i & 63;
        Y[(((size_t)(b * CC + c)) << 12) + n0 + q] = Ps[q * FP + c];
    }
}
#define FLASH_SMEM ((4 * 64 * FP + 128) * (int)sizeof(float))

// ---------------- 1x1 conv + bias + residual --------------------------------
// grid 256 blocks x 256 threads; thread: 1 position (b,n), 16 output channels
__global__ void __launch_bounds__(256) w1x1_res_kernel(
    const float* __restrict__ y, const float* __restrict__ Ww,
    const float* __restrict__ Wb, const float* __restrict__ x,
    float* __restrict__ z)
{
    __shared__ float Ws[64 * 65];   // [ic][oc], padded
    int tid = threadIdx.x;
    for (int i = tid; i < 4096; i += 256) {
        int oc = i >> 6, ic = i & 63;
        Ws[ic * 65 + oc] = Ww[i];
    }
    __syncthreads();

    int og = tid & 3;
    int nl = tid >> 2;
    int gpos = blockIdx.x * 64 + nl;      // 0..16383
    int b = gpos >> 12, n = gpos & 4095;
    int oc0 = og * 16;

    float acc[16];
#pragma unroll
    for (int j = 0; j < 16; j++)
        acc[j] = Wb[oc0 + j] + x[(((size_t)(b * CC + oc0 + j)) << 12) + n];

    for (int ic = 0; ic < 64; ic++) {
        float v = y[(((size_t)(b * CC + ic)) << 12) + n];
#pragma unroll
        for (int j = 0; j < 16; j++)
            acc[j] = fmaf(v, Ws[ic * 65 + oc0 + j], acc[j]);
    }
#pragma unroll
    for (int j = 0; j < 16; j++)
        z[(((size_t)(b * CC + oc0 + j)) << 12) + n] = acc[j];
}

// ---------------- driver -----------------------------------------------------
extern "C" void kernel_launch(void* const* d_in, const int* in_sizes, int n_in,
                              void* d_out, int out_size)
{
    const float* x       = (const float*)d_in[0];
    const float* conv1_w = (const float*)d_in[1];
    const float* bn1_g   = (const float*)d_in[2];
    const float* bn1_b   = (const float*)d_in[3];
    const float* theta_w = (const float*)d_in[4];
    const float* theta_b = (const float*)d_in[5];
    const float* phi_w   = (const float*)d_in[6];
    const float* phi_b   = (const float*)d_in[7];
    const float* g_w     = (const float*)d_in[8];
    const float* g_b     = (const float*)d_in[9];
    const float* W_w     = (const float*)d_in[10];
    const float* W_b     = (const float*)d_in[11];
    const float* conv2_w = (const float*)d_in[12];
    const float* bn2_g   = (const float*)d_in[13];
    const float* bn2_b   = (const float*)d_in[14];
    float* out = (float*)d_out;

    float* buf = nullptr;
    cudaGetSymbolAddress((void**)&buf, g_buf);
    float* raw   = buf + OFF_RAW;
    float* x1    = buf + OFF_X1;
    float* th    = buf + OFF_TH;
    float* phi   = buf + OFF_PHI;
    float* gbuf  = buf + OFF_G;
    float* ybuf  = buf + OFF_Y;
    float* zbuf  = buf + OFF_Z;
    float* wt    = buf + OFF_WT;
    float* scale = buf + OFF_SC;
    float* shift = buf + OFF_SH;

    cudaFuncSetAttribute(flash_kernel,
                         cudaFuncAttributeMaxDynamicSharedMemorySize, FLASH_SMEM);

    dim3 convGrid(WWD / 16, HH / 8, BB);

    // conv1 -> BN -> ReLU
    wtrans_kernel<<<144, 256>>>(conv1_w, wt);
    conv3x3_kernel<<<convGrid, 256>>>(x, wt, nullptr, raw, 0);
    bn_stats_kernel<<<64, 256>>>(raw, bn1_g, bn1_b, scale, shift);
    bn_apply_relu_kernel<<<4096, 256>>>(raw, scale, shift, x1);

    // theta (transposed out), phi, g (transposed out)
    wtrans_kernel<<<144, 256>>>(theta_w, wt);
    conv3x3_kernel<<<convGrid, 256>>>(x1, wt, theta_b, th, 1);
    wtrans_kernel<<<144, 256>>>(phi_w, wt);
    conv3x3_kernel<<<convGrid, 256>>>(x1, wt, phi_b, phi, 0);
    wtrans_kernel<<<144, 256>>>(g_w, wt);
    conv3x3_kernel<<<convGrid, 256>>>(x1, wt, g_b, gbuf, 1);

    // attention
    flash_kernel<<<dim3(NN / 64, BB), 128, FLASH_SMEM>>>(th, phi, gbuf, ybuf);

    // 1x1 W conv + residual
    w1x1_res_kernel<<<256, 256>>>(ybuf, W_w, W_b, x, zbuf);

    // conv2 -> BN -> ReLU -> out
    wtrans_kernel<<<144, 256>>>(conv2_w, wt);
    conv3x3_kernel<<<convGrid, 256>>>(zbuf, wt, nullptr, raw, 0);
    bn_stats_kernel<<<64, 256>>>(raw, bn2_g, bn2_b, scale, shift);
    bn_apply_relu_kernel<<<4096, 256>>>(raw, scale, shift, out);
}

// round 3
// speedup vs baseline: 2.0614x; 2.0614x over previous
#include <cuda_runtime.h>
#include <math.h>
#include <stdint.h>

#define CC 64
#define HH 64
#define WWD 64
#define NN 4096
#define BB 4

// ---------------- scratch (static device memory; no allocs allowed) ----------
__device__ float g_buf[8u * 1024u * 1024u];

static const size_t OFF_RAW = 0;
static const size_t OFF_X1  = 1u << 20;
static const size_t OFF_TH  = 2u << 20;
static const size_t OFF_PHI = 3u << 20;
static const size_t OFF_G   = 4u << 20;
static const size_t OFF_Y   = 5u << 20;
static const size_t OFF_Z   = 6u << 20;
static const size_t OFF_WT  = 7u << 20;
static const size_t OFF_SC  = OFF_WT + 40960;
static const size_t OFF_SH  = OFF_SC + 64;

// ---------------- weight transpose: w[oc][ic][k] -> wt[(ic*9+k)*64 + oc] -----
__global__ void wtrans_kernel(const float* __restrict__ w, float* __restrict__ wt) {
    int i = blockIdx.x * 256 + threadIdx.x;
    if (i >= CC * CC * 9) return;
    int oc  = i / (CC * 9);
    int rem = i - oc * (CC * 9);
    wt[rem * CC + oc] = w[i];
}

// ---------------- 3x3 conv, pad=1 -------------------------------------------
__global__ void __launch_bounds__(256) conv3x3_kernel(
    const float* __restrict__ in, const float* __restrict__ wt,
    const float* __restrict__ bias, float* __restrict__ out, int transpose_out)
{
    __shared__ __align__(16) float in_s[8][10][18];
    __shared__ __align__(16) float w_s[8 * 9 * 64];

    int b   = blockIdx.z;
    int ty0 = blockIdx.y * 8;
    int tx0 = blockIdx.x * 16;
    int tid = threadIdx.x;
    int pt  = tid & 31;
    int px  = pt & 15;
    int py  = (pt >> 4) * 4;
    int oc0 = (tid >> 5) * 8;

    float acc[4][8];
#pragma unroll
    for (int i = 0; i < 4; i++)
#pragma unroll
        for (int j = 0; j < 8; j++) acc[i][j] = 0.f;

    for (int ic0 = 0; ic0 < CC; ic0 += 8) {
        for (int i = tid; i < 8 * 10 * 18; i += 256) {
            int ic  = i / 180;
            int rem = i - ic * 180;
            int r   = rem / 18;
            int c   = rem - r * 18;
            int gy  = ty0 + r - 1;
            int gx  = tx0 + c - 1;
            float v = 0.f;
            if (gy >= 0 && gy < HH && gx >= 0 && gx < WWD)
                v = in[((size_t)(b * CC + ic0 + ic) * HH + gy) * WWD + gx];
            in_s[ic][r][c] = v;
        }
        for (int i = tid; i < 8 * 9 * 64; i += 256)
            w_s[i] = wt[ic0 * 9 * 64 + i];
        __syncthreads();

#pragma unroll 2
        for (int ic = 0; ic < 8; ic++) {
#pragma unroll
            for (int ky = 0; ky < 3; ky++) {
#pragma unroll
                for (int kx = 0; kx < 3; kx++) {
                    const float* wb = &w_s[(ic * 9 + ky * 3 + kx) * 64 + oc0];
                    float4 wa = *(const float4*)wb;
                    float4 wc = *(const float4*)(wb + 4);
#pragma unroll
                    for (int i = 0; i < 4; i++) {
                        float v = in_s[ic][py + i + ky][px + kx];
                        acc[i][0] = fmaf(v, wa.x, acc[i][0]);
                        acc[i][1] = fmaf(v, wa.y, acc[i][1]);
                        acc[i][2] = fmaf(v, wa.z, acc[i][2]);
                        acc[i][3] = fmaf(v, wa.w, acc[i][3]);
                        acc[i][4] = fmaf(v, wc.x, acc[i][4]);
                        acc[i][5] = fmaf(v, wc.y, acc[i][5]);
                        acc[i][6] = fmaf(v, wc.z, acc[i][6]);
                        acc[i][7] = fmaf(v, wc.w, acc[i][7]);
                    }
                }
            }
        }
        __syncthreads();
    }

    float bv[8];
#pragma unroll
    for (int j = 0; j < 8; j++) bv[j] = bias ? bias[oc0 + j] : 0.f;

#pragma unroll
    for (int i = 0; i < 4; i++) {
        int gy = ty0 + py + i;
        int gx = tx0 + px;
        int n  = gy * WWD + gx;
#pragma unroll
        for (int j = 0; j < 8; j++) {
            float v = acc[i][j] + bv[j];
            if (transpose_out)
                out[((size_t)b * NN + n) * CC + oc0 + j] = v;
            else
                out[((size_t)(b * CC + oc0 + j) << 12) + n] = v;
        }
    }
}

// ---------------- BN stats ----------------------------------------------------
__global__ void bn_stats_kernel(const float* __restrict__ in,
                                const float* __restrict__ gamma,
                                const float* __restrict__ beta,
                                float* __restrict__ scale, float* __restrict__ shift)
{
    int c = blockIdx.x;
    int tid = threadIdx.x;
    float s = 0.f, s2 = 0.f;
    for (int b = 0; b < BB; b++) {
        const float* p = in + (((size_t)(b * CC + c)) << 12);
        for (int i = tid; i < NN; i += 256) {
            float v = p[i];
            s += v; s2 += v * v;
        }
    }
    __shared__ float sh[256], sh2[256];
    sh[tid] = s; sh2[tid] = s2;
    __syncthreads();
    for (int o = 128; o > 0; o >>= 1) {
        if (tid < o) { sh[tid] += sh[tid + o]; sh2[tid] += sh2[tid + o]; }
        __syncthreads();
    }
    if (tid == 0) {
        const float inv = 1.f / (float)(BB * NN);
        float mean = sh[0] * inv;
        float var  = sh2[0] * inv - mean * mean;
        float r    = rsqrtf(var + 1e-5f);
        float sc   = gamma[c] * r;
        scale[c] = sc;
        shift[c] = beta[c] - mean * sc;
    }
}

__global__ void bn_apply_relu_kernel(const float* __restrict__ in,
                                     const float* __restrict__ scale,
                                     const float* __restrict__ shift,
                                     float* __restrict__ out)
{
    int i = blockIdx.x * 256 + threadIdx.x;
    int c = (i >> 12) & 63;
    float v = fmaf(in[i], scale[c], shift[c]);
    out[i] = fmaxf(v, 0.f);
}

// ---------------- tf32 mma helpers -------------------------------------------
__device__ __forceinline__ uint32_t cvt_tf32(float f) {
    uint32_t r;
    asm("cvt.rna.tf32.f32 %0, %1;" : "=r"(r) : "f"(f));
    return r;
}

__device__ __forceinline__ void mma_tf32(float c[4], const uint32_t a[4],
                                         uint32_t b0, uint32_t b1) {
    asm volatile(
        "mma.sync.aligned.m16n8k8.row.col.f32.tf32.tf32.f32 "
        "{%0,%1,%2,%3}, {%4,%5,%6,%7}, {%8,%9}, {%0,%1,%2,%3};"
        : "+f"(c[0]), "+f"(c[1]), "+f"(c[2]), "+f"(c[3])
        : "r"(a[0]), "r"(a[1]), "r"(a[2]), "r"(a[3]), "r"(b0), "r"(b1));
}

// ---------------- flash attention with tf32 tensor cores ---------------------
// Qt: [B,N,C], K(phi): [B,C,N], Gt: [B,N,C] -> Y: [B,C,N]
// 128 threads = 4 warps; block tile Br=64 queries x Bc=64 keys, d=64.
// Warp w owns query rows 16w..16w+15 as m16n8k8 A-fragments held in registers.
// KP=72: 72 mod 32 == 8 makes B-fragment LDS (addr = (8k+tig)*KP + 8nt+gid)
// conflict-free (banks 8*tig + gid distinct over the warp).
#define KP 72
__global__ void __launch_bounds__(128) flash_tf32_kernel(
    const float* __restrict__ Qt, const float* __restrict__ K,
    const float* __restrict__ Gt, float* __restrict__ Y)
{
    extern __shared__ __align__(16) float sm[];
    float* Ks = sm;                 // [c=64][KP]  (B for S; reused as O stage)
    float* Gs = sm + 64 * KP;       // [m=64][KP]  (B for PV)
    float* Ps = sm + 128 * KP;      // 4 warps x [16][KP] (P round-trip)

    int b   = blockIdx.y;
    int n0  = blockIdx.x * 64;
    int tid = threadIdx.x;
    int w    = tid >> 5;
    int lane = tid & 31;
    int gid  = lane >> 2;   // groupID (row within 8)
    int tig  = lane & 3;    // thread-in-group
    float* Pw = Ps + w * 16 * KP;

    // ---- load Q fragments (held in regs all kernel) ----
    uint32_t aq[8][4];
    {
        const float* qb = Qt + ((size_t)b * NN + n0 + w * 16) * CC;
#pragma unroll
        for (int k = 0; k < 8; k++) {
            aq[k][0] = cvt_tf32(qb[(size_t)gid * CC + 8 * k + tig]);
            aq[k][1] = cvt_tf32(qb[(size_t)(gid + 8) * CC + 8 * k + tig]);
            aq[k][2] = cvt_tf32(qb[(size_t)gid * CC + 8 * k + 4 + tig]);
            aq[k][3] = cvt_tf32(qb[(size_t)(gid + 8) * CC + 8 * k + 4 + tig]);
        }
    }

    float o[8][4];
#pragma unroll
    for (int nt = 0; nt < 8; nt++)
#pragma unroll
        for (int r = 0; r < 4; r++) o[nt][r] = 0.f;
    float rm0 = -1e30f, rm1 = -1e30f, rl0 = 0.f, rl1 = 0.f;

    for (int j0 = 0; j0 < NN; j0 += 64) {
        __syncthreads();   // everyone done reading previous Ks/Gs
        // ---- load K,G tiles (convert to tf32 bits at store) ----
        for (int idx = tid; idx < 1024; idx += 128) {
            int row = idx >> 4;
            int c4  = (idx & 15) << 2;
            float4 kv = *(const float4*)(K + (((size_t)(b * CC + row)) << 12) + j0 + c4);
            uint4 kb;
            kb.x = cvt_tf32(kv.x); kb.y = cvt_tf32(kv.y);
            kb.z = cvt_tf32(kv.z); kb.w = cvt_tf32(kv.w);
            *(uint4*)(Ks + row * KP + c4) = kb;
            float4 gv = *(const float4*)(Gt + ((size_t)b * NN + j0 + row) * CC + c4);
            uint4 gb;
            gb.x = cvt_tf32(gv.x); gb.y = cvt_tf32(gv.y);
            gb.z = cvt_tf32(gv.z); gb.w = cvt_tf32(gv.w);
            *(uint4*)(Gs + row * KP + c4) = gb;
        }
        __syncthreads();

        // ---- S = Q K : 8 k-steps x 8 n-tiles ----
        float s[8][4];
#pragma unroll
        for (int nt = 0; nt < 8; nt++)
#pragma unroll
            for (int r = 0; r < 4; r++) s[nt][r] = 0.f;

#pragma unroll
        for (int kk = 0; kk < 8; kk++) {
            const float* kr0 = Ks + (8 * kk + tig) * KP + gid;
            const float* kr1 = Ks + (8 * kk + tig + 4) * KP + gid;
#pragma unroll
            for (int nt = 0; nt < 8; nt++) {
                uint32_t b0 = __float_as_uint(kr0[8 * nt]);
                uint32_t b1 = __float_as_uint(kr1[8 * nt]);
                mma_tf32(s[nt], aq[kk], b0, b1);
            }
        }

        // ---- online softmax on C-fragment layout ----
        float mx0 = -1e30f, mx1 = -1e30f;
#pragma unroll
        for (int nt = 0; nt < 8; nt++) {
            mx0 = fmaxf(mx0, fmaxf(s[nt][0], s[nt][1]));
            mx1 = fmaxf(mx1, fmaxf(s[nt][2], s[nt][3]));
        }
        mx0 = fmaxf(mx0, __shfl_xor_sync(0xffffffffu, mx0, 1));
        mx0 = fmaxf(mx0, __shfl_xor_sync(0xffffffffu, mx0, 2));
        mx1 = fmaxf(mx1, __shfl_xor_sync(0xffffffffu, mx1, 1));
        mx1 = fmaxf(mx1, __shfl_xor_sync(0xffffffffu, mx1, 2));

        float mn0 = fmaxf(rm0, mx0), mn1 = fmaxf(rm1, mx1);
        float al0 = __expf(rm0 - mn0), al1 = __expf(rm1 - mn1);
        rm0 = mn0; rm1 = mn1;

        float rs0 = 0.f, rs1 = 0.f;
#pragma unroll
        for (int nt = 0; nt < 8; nt++) {
            float p0 = __expf(s[nt][0] - mn0);
            float p1 = __expf(s[nt][1] - mn0);
            float p2 = __expf(s[nt][2] - mn1);
            float p3 = __expf(s[nt][3] - mn1);
            rs0 += p0 + p1; rs1 += p2 + p3;
            uint2 v01; v01.x = cvt_tf32(p0); v01.y = cvt_tf32(p1);
            uint2 v23; v23.x = cvt_tf32(p2); v23.y = cvt_tf32(p3);
            *(uint2*)(Pw + gid * KP + 8 * nt + 2 * tig) = v01;
            *(uint2*)(Pw + (gid + 8) * KP + 8 * nt + 2 * tig) = v23;
        }
        rs0 += __shfl_xor_sync(0xffffffffu, rs0, 1);
        rs0 += __shfl_xor_sync(0xffffffffu, rs0, 2);
        rs1 += __shfl_xor_sync(0xffffffffu, rs1, 1);
        rs1 += __shfl_xor_sync(0xffffffffu, rs1, 2);
        rl0 = rl0 * al0 + rs0;
        rl1 = rl1 * al1 + rs1;

#pragma unroll
        for (int nt = 0; nt < 8; nt++) {
            o[nt][0] *= al0; o[nt][1] *= al0;
            o[nt][2] *= al1; o[nt][3] *= al1;
        }
        __syncwarp();   // P written cross-thread within warp

        // ---- O += P G ----
#pragma unroll
        for (int kk = 0; kk < 8; kk++) {
            uint32_t pa[4];
            pa[0] = __float_as_uint(Pw[gid * KP + 8 * kk + tig]);
            pa[1] = __float_as_uint(Pw[(gid + 8) * KP + 8 * kk + tig]);
            pa[2] = __float_as_uint(Pw[gid * KP + 8 * kk + 4 + tig]);
            pa[3] = __float_as_uint(Pw[(gid + 8) * KP + 8 * kk + 4 + tig]);
            const float* gr0 = Gs + (8 * kk + tig) * KP + gid;
            const float* gr1 = Gs + (8 * kk + tig + 4) * KP + gid;
#pragma unroll
            for (int nt = 0; nt < 8; nt++) {
                uint32_t b0 = __float_as_uint(gr0[8 * nt]);
                uint32_t b1 = __float_as_uint(gr1[8 * nt]);
                mma_tf32(o[nt], pa, b0, b1);
            }
        }
    }

    // ---- epilogue: normalize, stage [q][c] in smem, coalesced write ----
    __syncthreads();
    float li0 = 1.f / rl0, li1 = 1.f / rl1;
    float* Os = Ks;   // reuse
#pragma unroll
    for (int nt = 0; nt < 8; nt++) {
        float2 v0; v0.x = o[nt][0] * li0; v0.y = o[nt][1] * li0;
        float2 v1; v1.x = o[nt][2] * li1; v1.y = o[nt][3] * li1;
        *(float2*)(Os + (w * 16 + gid) * KP + 8 * nt + 2 * tig) = v0;
        *(float2*)(Os + (w * 16 + gid + 8) * KP + 8 * nt + 2 * tig) = v1;
    }
    __syncthreads();
    for (int i = tid; i < 4096; i += 128) {
        int c = i >> 6, q = i & 63;
        Y[(((size_t)(b * CC + c)) << 12) + n0 + q] = Os[q * KP + c];
    }
}
#define FLASH_SMEM ((192 * KP) * (int)sizeof(float))

// ---------------- 1x1 conv + bias + residual ---------------------------------
__global__ void __launch_bounds__(256) w1x1_res_kernel(
    const float* __restrict__ y, const float* __restrict__ Ww,
    const float* __restrict__ Wb, const float* __restrict__ x,
    float* __restrict__ z)
{
    __shared__ float Ws[64 * 65];
    int tid = threadIdx.x;
    for (int i = tid; i < 4096; i += 256) {
        int oc = i >> 6, ic = i & 63;
        Ws[ic * 65 + oc] = Ww[i];
    }
    __syncthreads();

    int og = tid & 3;
    int nl = tid >> 2;
    int gpos = blockIdx.x * 64 + nl;
    int b = gpos >> 12, n = gpos & 4095;
    int oc0 = og * 16;

    float acc[16];
#pragma unroll
    for (int j = 0; j < 16; j++)
        acc[j] = Wb[oc0 + j] + x[(((size_t)(b * CC + oc0 + j)) << 12) + n];

    for (int ic = 0; ic < 64; ic++) {
        float v = y[(((size_t)(b * CC + ic)) << 12) + n];
#pragma unroll
        for (int j = 0; j < 16; j++)
            acc[j] = fmaf(v, Ws[ic * 65 + oc0 + j], acc[j]);
    }
#pragma unroll
    for (int j = 0; j < 16; j++)
        z[(((size_t)(b * CC + oc0 + j)) << 12) + n] = acc[j];
}

// ---------------- driver -----------------------------------------------------
extern "C" void kernel_launch(void* const* d_in, const int* in_sizes, int n_in,
                              void* d_out, int out_size)
{
    const float* x       = (const float*)d_in[0];
    const float* conv1_w = (const float*)d_in[1];
    const float* bn1_g   = (const float*)d_in[2];
    const float* bn1_b   = (const float*)d_in[3];
    const float* theta_w = (const float*)d_in[4];
    const float* theta_b = (const float*)d_in[5];
    const float* phi_w   = (const float*)d_in[6];
    const float* phi_b   = (const float*)d_in[7];
    const float* g_w     = (const float*)d_in[8];
    const float* g_b     = (const float*)d_in[9];
    const float* W_w     = (const float*)d_in[10];
    const float* W_b     = (const float*)d_in[11];
    const float* conv2_w = (const float*)d_in[12];
    const float* bn2_g   = (const float*)d_in[13];
    const float* bn2_b   = (const float*)d_in[14];
    float* out = (float*)d_out;

    float* buf = nullptr;
    cudaGetSymbolAddress((void**)&buf, g_buf);
    float* raw   = buf + OFF_RAW;
    float* x1    = buf + OFF_X1;
    float* th    = buf + OFF_TH;
    float* phi   = buf + OFF_PHI;
    float* gbuf  = buf + OFF_G;
    float* ybuf  = buf + OFF_Y;
    float* zbuf  = buf + OFF_Z;
    float* wt    = buf + OFF_WT;
    float* scale = buf + OFF_SC;
    float* shift = buf + OFF_SH;

    cudaFuncSetAttribute(flash_tf32_kernel,
                         cudaFuncAttributeMaxDynamicSharedMemorySize, FLASH_SMEM);

    dim3 convGrid(WWD / 16, HH / 8, BB);

    // conv1 -> BN -> ReLU
    wtrans_kernel<<<144, 256>>>(conv1_w, wt);
    conv3x3_kernel<<<convGrid, 256>>>(x, wt, nullptr, raw, 0);
    bn_stats_kernel<<<64, 256>>>(raw, bn1_g, bn1_b, scale, shift);
    bn_apply_relu_kernel<<<4096, 256>>>(raw, scale, shift, x1);

    // theta (transposed out), phi, g (transposed out)
    wtrans_kernel<<<144, 256>>>(theta_w, wt);
    conv3x3_kernel<<<convGrid, 256>>>(x1, wt, theta_b, th, 1);
    wtrans_kernel<<<144, 256>>>(phi_w, wt);
    conv3x3_kernel<<<convGrid, 256>>>(x1, wt, phi_b, phi, 0);
    wtrans_kernel<<<144, 256>>>(g_w, wt);
    conv3x3_kernel<<<convGrid, 256>>>(x1, wt, g_b, gbuf, 1);

    // attention (tf32 tensor cores)
    flash_tf32_kernel<<<dim3(NN / 64, BB), 128, FLASH_SMEM>>>(th, phi, gbuf, ybuf);

    // 1x1 W conv + residual
    w1x1_res_kernel<<<256, 256>>>(ybuf, W_w, W_b, x, zbuf);

    // conv2 -> BN -> ReLU -> out
    wtrans_kernel<<<144, 256>>>(conv2_w, wt);
    conv3x3_kernel<<<convGrid, 256>>>(zbuf, wt, nullptr, raw, 0);
    bn_stats_kernel<<<64, 256>>>(raw, bn2_g, bn2_b, scale, shift);
    bn_apply_relu_kernel<<<4096, 256>>>(raw, scale, shift, out);
}

// round 4
// speedup vs baseline: 2.7708x; 1.3441x over previous
#include <cuda_runtime.h>
#include <math.h>
#include <stdint.h>

#define CC 64
#define HH 64
#define WWD 64
#define NN 4096
#define BB 4
#define WSET (576 * 64)

// ---------------- scratch (static device memory; no allocs allowed) ----------
__device__ float g_buf[12u * 1024u * 1024u];

static const size_t OFF_RAW = 0;
static const size_t OFF_X1H = 1u << 20;
static const size_t OFF_X1L = 2u << 20;
static const size_t OFF_TH  = 3u << 20;
static const size_t OFF_PHI = 4u << 20;
static const size_t OFF_G   = 5u << 20;
static const size_t OFF_Y   = 6u << 20;
static const size_t OFF_ZH  = 7u << 20;
static const size_t OFF_ZL  = 8u << 20;
static const size_t OFF_XH  = 9u << 20;
static const size_t OFF_XL  = 10u << 20;
static const size_t OFF_WTH = 11u << 20;                 // 5*36864
static const size_t OFF_WTL = OFF_WTH + 5 * 36864;
static const size_t OFF_SC  = OFF_WTL + 5 * 36864;
static const size_t OFF_SH  = OFF_SC + 64;

// ---------------- tf32 helpers -----------------------------------------------
__device__ __forceinline__ uint32_t cvt_tf32(float f) {
    uint32_t r;
    asm("cvt.rna.tf32.f32 %0, %1;" : "=r"(r) : "f"(f));
    return r;
}

__device__ __forceinline__ void mma_tf32(float c[4], const uint32_t a[4],
                                         uint32_t b0, uint32_t b1) {
    asm volatile(
        "mma.sync.aligned.m16n8k8.row.col.f32.tf32.tf32.f32 "
        "{%0,%1,%2,%3}, {%4,%5,%6,%7}, {%8,%9}, {%0,%1,%2,%3};"
        : "+f"(c[0]), "+f"(c[1]), "+f"(c[2]), "+f"(c[3])
        : "r"(a[0]), "r"(a[1]), "r"(a[2]), "r"(a[3]), "r"(b0), "r"(b1));
}

// ---------------- weight prep: 5 sets -> k-major hi/lo ------------------------
// src w[oc][ic][tap]; dst row = (ic>>3)*72 + tap*8 + (ic&7); [row][oc]
__global__ void wtrans_all_kernel(
    const float* __restrict__ w0, const float* __restrict__ w1,
    const float* __restrict__ w2, const float* __restrict__ w3,
    const float* __restrict__ w4, float* __restrict__ wh, float* __restrict__ wl)
{
    int i = blockIdx.x * 256 + threadIdx.x;
    if (i >= 5 * 36864) return;
    int s = i / 36864;
    int r = i - s * 36864;
    const float* w = (s == 0) ? w0 : (s == 1) ? w1 : (s == 2) ? w2 : (s == 3) ? w3 : w4;
    int oc  = r / 576;
    int r2  = r - oc * 576;
    int ic  = r2 / 9;
    int tap = r2 - ic * 9;
    float v = w[r];
    int row  = (ic >> 3) * 72 + tap * 8 + (ic & 7);
    int didx = s * 36864 + row * 64 + oc;
    uint32_t h = cvt_tf32(v);
    wh[didx] = __uint_as_float(h);
    wl[didx] = __uint_as_float(cvt_tf32(v - __uint_as_float(h)));
}

// ---------------- split fp32 -> tf32 hi/lo ------------------------------------
__global__ void split_kernel(const float* __restrict__ in,
                             float* __restrict__ hi, float* __restrict__ lo)
{
    int i = blockIdx.x * 256 + threadIdx.x;
    float v = in[i];
    uint32_t h = cvt_tf32(v);
    hi[i] = __uint_as_float(h);
    lo[i] = __uint_as_float(cvt_tf32(v - __uint_as_float(h)));
}

// ---------------- 3x3 conv via tf32 tensor cores (3xTF32 precision) -----------
// Block: 64 oc x 128 px (2 rows). 4 warps, each 64m x 32n.
// k ordering: chunk(8ic) -> tap -> icL; each 8-wide k-step = one tap.
__global__ void __launch_bounds__(128) conv3x3_mma_kernel(
    const float* __restrict__ in_hi, const float* __restrict__ in_lo,
    const float* __restrict__ whi, const float* __restrict__ wlo,
    const float* __restrict__ bias0, const float* __restrict__ bias1,
    const float* __restrict__ bias2,
    float* __restrict__ out0, float* __restrict__ out1, float* __restrict__ out2,
    int trans_mask)
{
    extern __shared__ __align__(16) float sm[];
    float* wh_s = sm;             // 72*72 = 5184
    float* wl_s = sm + 5184;      // 5184
    float* ih_s = sm + 10368;     // 8*296 = 2368
    float* il_s = sm + 12736;     // 2368

    int s = blockIdx.z;
    const float* bias = (s == 0) ? bias0 : (s == 1) ? bias1 : bias2;
    float* out = (s == 0) ? out0 : (s == 1) ? out1 : out2;
    int trans = (trans_mask >> s) & 1;
    const float* wh = whi + (size_t)s * WSET;
    const float* wl = wlo + (size_t)s * WSET;

    int b   = blockIdx.y;
    int y0  = blockIdx.x * 2;
    int tid = threadIdx.x;
    int w    = tid >> 5;
    int lane = tid & 31;
    int gid  = lane >> 2;
    int tig  = lane & 3;
    int wy = w >> 1;            // output row within pair for this warp
    int wx = (w & 1) * 32;      // x offset for this warp

    float c[4][4][4];           // [mt][ntl][reg]
#pragma unroll
    for (int mt = 0; mt < 4; mt++)
#pragma unroll
        for (int nt = 0; nt < 4; nt++)
#pragma unroll
            for (int r = 0; r < 4; r++) c[mt][nt][r] = 0.f;

    for (int ch = 0; ch < 8; ch++) {
        __syncthreads();
        // weights: 72 rows x 64 oc, hi+lo (contiguous float4 LDG)
        for (int i = tid; i < 1152; i += 128) {
            float4 vh = *(const float4*)(wh + ch * 4608 + i * 4);
            float4 vl = *(const float4*)(wl + ch * 4608 + i * 4);
            int r  = i >> 4;
            int c4 = (i & 15) << 2;
            *(float4*)(wh_s + r * 72 + c4) = vh;
            *(float4*)(wl_s + r * 72 + c4) = vl;
        }
        // input: 8 ic x 4 rows x 66 cols (zero-padded borders)
        for (int i = tid; i < 2112; i += 128) {
            int icL = i / 264;
            int rem = i - icL * 264;
            int iy  = rem / 66;
            int col = rem - iy * 66;
            int gy = y0 + iy - 1;
            int gx = col - 1;
            float vh = 0.f, vl = 0.f;
            if (gy >= 0 && gy < HH && gx >= 0 && gx < WWD) {
                size_t gixd = (((size_t)(b * CC + ch * 8 + icL)) << 12) + gy * WWD + gx;
                vh = in_hi[gixd];
                vl = in_lo[gixd];
            }
            ih_s[icL * 296 + iy * 72 + col] = vh;
            il_s[icL * 296 + iy * 72 + col] = vl;
        }
        __syncthreads();

#pragma unroll
        for (int kk = 0; kk < 9; kk++) {
            int ky = kk / 3, kx = kk - ky * 3;
            // B fragments (shared across all 4 m-tiles)
            uint32_t bh0[4], bh1[4], bl0[4], bl1[4];
#pragma unroll
            for (int nt = 0; nt < 4; nt++) {
                int base = tig * 296 + (ky + wy) * 72 + kx + wx + nt * 8 + gid;
                bh0[nt] = __float_as_uint(ih_s[base]);
                bh1[nt] = __float_as_uint(ih_s[base + 4 * 296]);
                bl0[nt] = __float_as_uint(il_s[base]);
                bl1[nt] = __float_as_uint(il_s[base + 4 * 296]);
            }
#pragma unroll
            for (int mt = 0; mt < 4; mt++) {
                int colA = mt * 16 + gid;
                int r0 = (kk * 8 + tig) * 72;
                int r1 = (kk * 8 + tig + 4) * 72;
                uint32_t ah[4], al[4];
                ah[0] = __float_as_uint(wh_s[r0 + colA]);
                ah[1] = __float_as_uint(wh_s[r0 + colA + 8]);
                ah[2] = __float_as_uint(wh_s[r1 + colA]);
                ah[3] = __float_as_uint(wh_s[r1 + colA + 8]);
                al[0] = __float_as_uint(wl_s[r0 + colA]);
                al[1] = __float_as_uint(wl_s[r0 + colA + 8]);
                al[2] = __float_as_uint(wl_s[r1 + colA]);
                al[3] = __float_as_uint(wl_s[r1 + colA + 8]);
#pragma unroll
                for (int nt = 0; nt < 4; nt++) {
                    mma_tf32(c[mt][nt], ah, bh0[nt], bh1[nt]);
                    mma_tf32(c[mt][nt], ah, bl0[nt], bl1[nt]);
                    mma_tf32(c[mt][nt], al, bh0[nt], bh1[nt]);
                }
            }
        }
    }

    // ---- epilogue: bias, stage [oc][128] pitch 130, coalesced write ----
    __syncthreads();
    float* Os = sm;   // 64*130 = 8320 floats, reuses weight smem
    float bv0[4], bv1[4];
#pragma unroll
    for (int mt = 0; mt < 4; mt++) {
        bv0[mt] = bias ? bias[mt * 16 + gid] : 0.f;
        bv1[mt] = bias ? bias[mt * 16 + gid + 8] : 0.f;
    }
#pragma unroll
    for (int mt = 0; mt < 4; mt++)
#pragma unroll
        for (int nt = 0; nt < 4; nt++) {
            int n = wx + wy * 64 + nt * 8 + 2 * tig;
            float2 v0, v1;
            v0.x = c[mt][nt][0] + bv0[mt];
            v0.y = c[mt][nt][1] + bv0[mt];
            v1.x = c[mt][nt][2] + bv1[mt];
            v1.y = c[mt][nt][3] + bv1[mt];
            *(float2*)(Os + (mt * 16 + gid) * 130 + n) = v0;
            *(float2*)(Os + (mt * 16 + gid + 8) * 130 + n) = v1;
        }
    __syncthreads();
    int n0 = blockIdx.x * 128;
    if (!trans) {
        for (int i = tid; i < 8192; i += 128) {
            int oc = i >> 7, nl = i & 127;
            out[(((size_t)(b * CC + oc)) << 12) + n0 + nl] = Os[oc * 130 + nl];
        }
    } else {
        for (int i = tid; i < 8192; i += 128) {
            int nl = i >> 6, oc = i & 63;
            out[((size_t)b * NN + n0 + nl) * CC + oc] = Os[oc * 130 + nl];
        }
    }
}
#define CONV_SMEM (15104 * (int)sizeof(float))

// ---------------- BN stats ----------------------------------------------------
__global__ void bn_stats_kernel(const float* __restrict__ in,
                                const float* __restrict__ gamma,
                                const float* __restrict__ beta,
                                float* __restrict__ scale, float* __restrict__ shift)
{
    int c = blockIdx.x;
    int tid = threadIdx.x;
    float s = 0.f, s2 = 0.f;
    for (int b = 0; b < BB; b++) {
        const float* p = in + (((size_t)(b * CC + c)) << 12);
        for (int i = tid; i < NN; i += 256) {
            float v = p[i];
            s += v; s2 += v * v;
        }
    }
    __shared__ float sh[256], sh2[256];
    sh[tid] = s; sh2[tid] = s2;
    __syncthreads();
    for (int o = 128; o > 0; o >>= 1) {
        if (tid < o) { sh[tid] += sh[tid + o]; sh2[tid] += sh2[tid + o]; }
        __syncthreads();
    }
    if (tid == 0) {
        const float inv = 1.f / (float)(BB * NN);
        float mean = sh[0] * inv;
        float var  = sh2[0] * inv - mean * mean;
        float r    = rsqrtf(var + 1e-5f);
        float sc   = gamma[c] * r;
        scale[c] = sc;
        shift[c] = beta[c] - mean * sc;
    }
}

__global__ void bn_apply_relu_kernel(const float* __restrict__ in,
                                     const float* __restrict__ scale,
                                     const float* __restrict__ shift,
                                     float* __restrict__ out)
{
    int i = blockIdx.x * 256 + threadIdx.x;
    int c = (i >> 12) & 63;
    float v = fmaf(in[i], scale[c], shift[c]);
    out[i] = fmaxf(v, 0.f);
}

__global__ void bn_apply_relu_split_kernel(const float* __restrict__ in,
                                           const float* __restrict__ scale,
                                           const float* __restrict__ shift,
                                           float* __restrict__ hi,
                                           float* __restrict__ lo)
{
    int i = blockIdx.x * 256 + threadIdx.x;
    int c = (i >> 12) & 63;
    float v = fmaxf(fmaf(in[i], scale[c], shift[c]), 0.f);
    uint32_t h = cvt_tf32(v);
    hi[i] = __uint_as_float(h);
    lo[i] = __uint_as_float(cvt_tf32(v - __uint_as_float(h)));
}

// ---------------- flash attention with tf32 tensor cores ---------------------
#define KP 72
__global__ void __launch_bounds__(128) flash_tf32_kernel(
    const float* __restrict__ Qt, const float* __restrict__ K,
    const float* __restrict__ Gt, float* __restrict__ Y)
{
    extern __shared__ __align__(16) float sm[];
    float* Ks = sm;
    float* Gs = sm + 64 * KP;
    float* Ps = sm + 128 * KP;

    int b   = blockIdx.y;
    int n0  = blockIdx.x * 64;
    int tid = threadIdx.x;
    int w    = tid >> 5;
    int lane = tid & 31;
    int gid  = lane >> 2;
    int tig  = lane & 3;
    float* Pw = Ps + w * 16 * KP;

    uint32_t aq[8][4];
    {
        const float* qb = Qt + ((size_t)b * NN + n0 + w * 16) * CC;
#pragma unroll
        for (int k = 0; k < 8; k++) {
            aq[k][0] = cvt_tf32(qb[(size_t)gid * CC + 8 * k + tig]);
            aq[k][1] = cvt_tf32(qb[(size_t)(gid + 8) * CC + 8 * k + tig]);
            aq[k][2] = cvt_tf32(qb[(size_t)gid * CC + 8 * k + 4 + tig]);
            aq[k][3] = cvt_tf32(qb[(size_t)(gid + 8) * CC + 8 * k + 4 + tig]);
        }
    }

    float o[8][4];
#pragma unroll
    for (int nt = 0; nt < 8; nt++)
#pragma unroll
        for (int r = 0; r < 4; r++) o[nt][r] = 0.f;
    float rm0 = -1e30f, rm1 = -1e30f, rl0 = 0.f, rl1 = 0.f;

    for (int j0 = 0; j0 < NN; j0 += 64) {
        __syncthreads();
        for (int idx = tid; idx < 1024; idx += 128) {
            int row = idx >> 4;
            int c4  = (idx & 15) << 2;
            float4 kv = *(const float4*)(K + (((size_t)(b * CC + row)) << 12) + j0 + c4);
            uint4 kb;
            kb.x = cvt_tf32(kv.x); kb.y = cvt_tf32(kv.y);
            kb.z = cvt_tf32(kv.z); kb.w = cvt_tf32(kv.w);
            *(uint4*)(Ks + row * KP + c4) = kb;
            float4 gv = *(const float4*)(Gt + ((size_t)b * NN + j0 + row) * CC + c4);
            uint4 gb;
            gb.x = cvt_tf32(gv.x); gb.y = cvt_tf32(gv.y);
            gb.z = cvt_tf32(gv.z); gb.w = cvt_tf32(gv.w);
            *(uint4*)(Gs + row * KP + c4) = gb;
        }
        __syncthreads();

        float s[8][4];
#pragma unroll
        for (int nt = 0; nt < 8; nt++)
#pragma unroll
            for (int r = 0; r < 4; r++) s[nt][r] = 0.f;

#pragma unroll
        for (int kk = 0; kk < 8; kk++) {
            const float* kr0 = Ks + (8 * kk + tig) * KP + gid;
            const float* kr1 = Ks + (8 * kk + tig + 4) * KP + gid;
#pragma unroll
            for (int nt = 0; nt < 8; nt++) {
                uint32_t b0 = __float_as_uint(kr0[8 * nt]);
                uint32_t b1 = __float_as_uint(kr1[8 * nt]);
                mma_tf32(s[nt], aq[kk], b0, b1);
            }
        }

        float mx0 = -1e30f, mx1 = -1e30f;
#pragma unroll
        for (int nt = 0; nt < 8; nt++) {
            mx0 = fmaxf(mx0, fmaxf(s[nt][0], s[nt][1]));
            mx1 = fmaxf(mx1, fmaxf(s[nt][2], s[nt][3]));
        }
        mx0 = fmaxf(mx0, __shfl_xor_sync(0xffffffffu, mx0, 1));
        mx0 = fmaxf(mx0, __shfl_xor_sync(0xffffffffu, mx0, 2));
        mx1 = fmaxf(mx1, __shfl_xor_sync(0xffffffffu, mx1, 1));
        mx1 = fmaxf(mx1, __shfl_xor_sync(0xffffffffu, mx1, 2));

        float mn0 = fmaxf(rm0, mx0), mn1 = fmaxf(rm1, mx1);
        float al0 = __expf(rm0 - mn0), al1 = __expf(rm1 - mn1);
        rm0 = mn0; rm1 = mn1;

        float rs0 = 0.f, rs1 = 0.f;
#pragma unroll
        for (int nt = 0; nt < 8; nt++) {
            float p0 = __expf(s[nt][0] - mn0);
            float p1 = __expf(s[nt][1] - mn0);
            float p2 = __expf(s[nt][2] - mn1);
            float p3 = __expf(s[nt][3] - mn1);
            rs0 += p0 + p1; rs1 += p2 + p3;
            uint2 v01; v01.x = cvt_tf32(p0); v01.y = cvt_tf32(p1);
            uint2 v23; v23.x = cvt_tf32(p2); v23.y = cvt_tf32(p3);
            *(uint2*)(Pw + gid * KP + 8 * nt + 2 * tig) = v01;
            *(uint2*)(Pw + (gid + 8) * KP + 8 * nt + 2 * tig) = v23;
        }
        rs0 += __shfl_xor_sync(0xffffffffu, rs0, 1);
        rs0 += __shfl_xor_sync(0xffffffffu, rs0, 2);
        rs1 += __shfl_xor_sync(0xffffffffu, rs1, 1);
        rs1 += __shfl_xor_sync(0xffffffffu, rs1, 2);
        rl0 = rl0 * al0 + rs0;
        rl1 = rl1 * al1 + rs1;

#pragma unroll
        for (int nt = 0; nt < 8; nt++) {
            o[nt][0] *= al0; o[nt][1] *= al0;
            o[nt][2] *= al1; o[nt][3] *= al1;
        }
        __syncwarp();

#pragma unroll
        for (int kk = 0; kk < 8; kk++) {
            uint32_t pa[4];
            pa[0] = __float_as_uint(Pw[gid * KP + 8 * kk + tig]);
            pa[1] = __float_as_uint(Pw[(gid + 8) * KP + 8 * kk + tig]);
            pa[2] = __float_as_uint(Pw[gid * KP + 8 * kk + 4 + tig]);
            pa[3] = __float_as_uint(Pw[(gid + 8) * KP + 8 * kk + 4 + tig]);
            const float* gr0 = Gs + (8 * kk + tig) * KP + gid;
            const float* gr1 = Gs + (8 * kk + tig + 4) * KP + gid;
#pragma unroll
            for (int nt = 0; nt < 8; nt++) {
                uint32_t b0 = __float_as_uint(gr0[8 * nt]);
                uint32_t b1 = __float_as_uint(gr1[8 * nt]);
                mma_tf32(o[nt], pa, b0, b1);
            }
        }
    }

    __syncthreads();
    float li0 = 1.f / rl0, li1 = 1.f / rl1;
    float* Os = Ks;
#pragma unroll
    for (int nt = 0; nt < 8; nt++) {
        float2 v0; v0.x = o[nt][0] * li0; v0.y = o[nt][1] * li0;
        float2 v1; v1.x = o[nt][2] * li1; v1.y = o[nt][3] * li1;
        *(float2*)(Os + (w * 16 + gid) * KP + 8 * nt + 2 * tig) = v0;
        *(float2*)(Os + (w * 16 + gid + 8) * KP + 8 * nt + 2 * tig) = v1;
    }
    __syncthreads();
    for (int i = tid; i < 4096; i += 128) {
        int c = i >> 6, q = i & 63;
        Y[(((size_t)(b * CC + c)) << 12) + n0 + q] = Os[q * KP + c];
    }
}
#define FLASH_SMEM ((192 * KP) * (int)sizeof(float))

// ---------------- 1x1 conv + bias + residual -> hi/lo split -------------------
__global__ void __launch_bounds__(256) w1x1_res_kernel(
    const float* __restrict__ y, const float* __restrict__ Ww,
    const float* __restrict__ Wb, const float* __restrict__ x,
    float* __restrict__ zh, float* __restrict__ zl)
{
    __shared__ float Ws[64 * 65];
    int tid = threadIdx.x;
    for (int i = tid; i < 4096; i += 256) {
        int oc = i >> 6, ic = i & 63;
        Ws[ic * 65 + oc] = Ww[i];
    }
    __syncthreads();

    int og = tid & 3;
    int nl = tid >> 2;
    int gpos = blockIdx.x * 64 + nl;
    int b = gpos >> 12, n = gpos & 4095;
    int oc0 = og * 16;

    float acc[16];
#pragma unroll
    for (int j = 0; j < 16; j++)
        acc[j] = Wb[oc0 + j] + x[(((size_t)(b * CC + oc0 + j)) << 12) + n];

    for (int ic = 0; ic < 64; ic++) {
        float v = y[(((size_t)(b * CC + ic)) << 12) + n];
#pragma unroll
        for (int j = 0; j < 16; j++)
            acc[j] = fmaf(v, Ws[ic * 65 + oc0 + j], acc[j]);
    }
#pragma unroll
    for (int j = 0; j < 16; j++) {
        size_t oidx = (((size_t)(b * CC + oc0 + j)) << 12) + n;
        float v = acc[j];
        uint32_t h = cvt_tf32(v);
        zh[oidx] = __uint_as_float(h);
        zl[oidx] = __uint_as_float(cvt_tf32(v - __uint_as_float(h)));
    }
}

// ---------------- driver -----------------------------------------------------
extern "C" void kernel_launch(void* const* d_in, const int* in_sizes, int n_in,
                              void* d_out, int out_size)
{
    const float* x       = (const float*)d_in[0];
    const float* conv1_w = (const float*)d_in[1];
    const float* bn1_g   = (const float*)d_in[2];
    const float* bn1_b   = (const float*)d_in[3];
    const float* theta_w = (const float*)d_in[4];
    const float* theta_b = (const float*)d_in[5];
    const float* phi_w   = (const float*)d_in[6];
    const float* phi_b   = (const float*)d_in[7];
    const float* g_w     = (const float*)d_in[8];
    const float* g_b     = (const float*)d_in[9];
    const float* W_w     = (const float*)d_in[10];
    const float* W_b     = (const float*)d_in[11];
    const float* conv2_w = (const float*)d_in[12];
    const float* bn2_g   = (const float*)d_in[13];
    const float* bn2_b   = (const float*)d_in[14];
    float* out = (float*)d_out;

    float* buf = nullptr;
    cudaGetSymbolAddress((void**)&buf, g_buf);
    float* raw   = buf + OFF_RAW;
    float* x1h   = buf + OFF_X1H;
    float* x1l   = buf + OFF_X1L;
    float* th    = buf + OFF_TH;
    float* phi   = buf + OFF_PHI;
    float* gbuf  = buf + OFF_G;
    float* ybuf  = buf + OFF_Y;
    float* zh    = buf + OFF_ZH;
    float* zl    = buf + OFF_ZL;
    float* xh    = buf + OFF_XH;
    float* xl    = buf + OFF_XL;
    float* wth   = buf + OFF_WTH;
    float* wtl   = buf + OFF_WTL;
    float* scale = buf + OFF_SC;
    float* shift = buf + OFF_SH;

    cudaFuncSetAttribute(flash_tf32_kernel,
                         cudaFuncAttributeMaxDynamicSharedMemorySize, FLASH_SMEM);
    cudaFuncSetAttribute(conv3x3_mma_kernel,
                         cudaFuncAttributeMaxDynamicSharedMemorySize, CONV_SMEM);

    // weight prep (all 5 sets) + input split
    wtrans_all_kernel<<<720, 256>>>(conv1_w, theta_w, phi_w, g_w, conv2_w, wth, wtl);
    split_kernel<<<4096, 256>>>(x, xh, xl);

    // conv1 -> BN -> ReLU (split output)
    conv3x3_mma_kernel<<<dim3(32, 4, 1), 128, CONV_SMEM>>>(
        xh, xl, wth, wtl, nullptr, nullptr, nullptr, raw, raw, raw, 0);
    bn_stats_kernel<<<64, 256>>>(raw, bn1_g, bn1_b, scale, shift);
    bn_apply_relu_split_kernel<<<4096, 256>>>(raw, scale, shift, x1h, x1l);

    // theta (trans), phi, g (trans) in one launch: sets 1,2,3 -> z = 0,1,2
    conv3x3_mma_kernel<<<dim3(32, 4, 3), 128, CONV_SMEM>>>(
        x1h, x1l, wth + 1 * WSET, wtl + 1 * WSET,
        theta_b, phi_b, g_b, th, phi, gbuf, 0b101);

    // attention (tf32 tensor cores)
    flash_tf32_kernel<<<dim3(NN / 64, BB), 128, FLASH_SMEM>>>(th, phi, gbuf, ybuf);

    // 1x1 W conv + residual -> split z
    w1x1_res_kernel<<<256, 256>>>(ybuf, W_w, W_b, x, zh, zl);

    // conv2 -> BN -> ReLU -> out
    conv3x3_mma_kernel<<<dim3(32, 4, 1), 128, CONV_SMEM>>>(
        zh, zl, wth + 4 * WSET, wtl + 4 * WSET,
        nullptr, nullptr, nullptr, raw, raw, raw, 0);
    bn_stats_kernel<<<64, 256>>>(raw, bn2_g, bn2_b, scale, shift);
    bn_apply_relu_kernel<<<4096, 256>>>(raw, scale, shift, out);
}